// round 14
// baseline (speedup 1.0000x reference)
#include <cuda_runtime.h>
#include <cuda_bf16.h>
#include <math.h>

#define BB 512
#define SS 1024
#define TT 52
#define START_TAG 50
#define END_TAG 51
#define LOG2E 1.4426950408889634f
#define LN2 0.6931471805599453

typedef unsigned long long ull;
typedef unsigned int u32;

// ---------------- device scratch (no allocations allowed) ----------------
__device__ __align__(16) float g_E[TT * TT];     // exp(transitions), f32
__device__ __align__(16) u32 g_EcBF[TT][28];     // col j: (E[2c][j],E[2c+1][j]) bf16x2
__device__ __align__(16) u32 g_ErBF[TT][28];     // row j: (E[j][2c],E[j][2c+1]) bf16x2
__device__ int    g_isU8;
__device__ __align__(16) int g_lenp[BB][4];
__device__ int    g_len[BB];
__device__ int    g_task[BB];                    // seq ids, length-descending
__device__ __align__(8) float g_alpha[BB][64];
__device__ __align__(8) float g_beta[BB][64];
__device__ int    g_Ka[BB], g_Kb[BB];
__device__ float  g_m0[BB];
__device__ double g_goldp[BB][4];
__device__ double g_final[BB];
__device__ unsigned g_cnt_len;
__device__ unsigned g_cnt_fin;

// ---------------- packed helpers ----------------
__device__ __forceinline__ ull f2pack(float lo, float hi) {
    ull r;
    asm("mov.b64 %0, {%1, %2};" : "=l"(r) : "f"(lo), "f"(hi));
    return r;
}
__device__ __forceinline__ float2 f2unpack(ull a) {
    float2 r;
    asm("mov.b64 {%0, %1}, %2;" : "=f"(r.x), "=f"(r.y) : "l"(a));
    return r;
}
__device__ __forceinline__ ull f2mul(ull a, ull b) {
    ull d;
    asm("mul.rn.f32x2 %0, %1, %2;" : "=l"(d) : "l"(a), "l"(b));
    return d;
}
__device__ __forceinline__ float ex2(float x) {
    float y;
    asm("ex2.approx.ftz.f32 %0, %1;" : "=f"(y) : "f"(x));
    return y;
}
__device__ __forceinline__ u32 bffma(u32 a, u32 b, u32 c) {
    u32 d;
    asm("fma.rn.bf16x2 %0, %1, %2, %3;" : "=r"(d) : "r"(a), "r"(b), "r"(c));
    return d;
}
__device__ __forceinline__ u32 bfadd(u32 a, u32 b) {
    u32 d;
    asm("add.rn.bf16x2 %0, %1, %2;" : "=r"(d) : "r"(a), "r"(b));
    return d;
}
__device__ __forceinline__ u32 packbf(float lo, float hi) {
    u32 d;   // PTX: first source -> upper half, second -> lower half
    asm("cvt.rn.bf16x2.f32 %0, %1, %2;" : "=r"(d) : "f"(hi), "f"(lo));
    return d;
}
__device__ __forceinline__ float bf2sum(u32 p) {
    float lo = __int_as_float(p << 16);
    float hi = __int_as_float(p & 0xFFFF0000u);
    return lo + hi;
}

// matvec over i=0..49: 25 bf16x2 fma, 4 accums
__device__ __forceinline__ float matvecbf(const u32* qw, const u32* Ep) {
    u32 a0 = bffma(qw[0], Ep[0], 0u);
    u32 a1 = bffma(qw[1], Ep[1], 0u);
    u32 a2 = bffma(qw[2], Ep[2], 0u);
    u32 a3 = bffma(qw[3], Ep[3], 0u);
    #pragma unroll
    for (int c = 4; c < 24; c += 4) {
        a0 = bffma(qw[c + 0], Ep[c + 0], a0);
        a1 = bffma(qw[c + 1], Ep[c + 1], a1);
        a2 = bffma(qw[c + 2], Ep[c + 2], a2);
        a3 = bffma(qw[c + 3], Ep[c + 3], a3);
    }
    a0 = bffma(qw[24], Ep[24], a0);
    a0 = bfadd(a0, a1);
    a2 = bfadd(a2, a3);
    a0 = bfadd(a0, a2);
    return bf2sum(a0);
}

// ---------------- mask dtype + E tables (f32 + packed bf16) --------------
__global__ void k_detect(const void* mask, const float* __restrict__ tr) {
    int tid = threadIdx.x;     // 256
    if (tid == 0) { g_cnt_len = 0; g_cnt_fin = 0; }
    if (tid < 32) {
        const unsigned char* p = (const unsigned char*)mask;
        int any = 0;
        for (int b = tid; b < BB; b += 32)
            any |= (int)p[(size_t)b * SS + 1];
        #pragma unroll
        for (int o = 16; o; o >>= 1) any |= __shfl_xor_sync(0xffffffffu, any, o);
        if (tid == 0) g_isU8 = (any != 0);
    }
    for (int idx = tid; idx < TT * TT; idx += 256)
        g_E[idx] = expf(tr[idx]);
    __syncthreads();
    for (int idx = tid; idx < TT * 28; idx += 256) {
        int j = idx / 28, c = idx % 28;
        u32 vc = 0, vr = 0;
        if (c < 25) {
            vc = packbf(g_E[(2 * c) * TT + j], g_E[(2 * c + 1) * TT + j]);
            vr = packbf(g_E[j * TT + 2 * c], g_E[j * TT + 2 * c + 1]);
        }
        g_EcBF[j][c] = vc;
        g_ErBF[j][c] = vr;
    }
}

// ---------------- length partials + fused rank (last block) --------------
__global__ void k_len(const void* mask) {
    int b   = blockIdx.x >> 2;
    int c   = blockIdx.x & 3;
    int tid = threadIdx.x;       // 256
    int s   = (c << 8) + tid;
    __shared__ int sc[8];
    __shared__ bool isLast;
    bool on;
    if (g_isU8) on = ((const unsigned char*)mask)[(size_t)b * SS + s] != 0;
    else        on = ((const unsigned int*)mask)[(size_t)b * SS + s] != 0;
    unsigned bal = __ballot_sync(0xffffffffu, on);
    if ((tid & 31) == 0) sc[tid >> 5] = __popc(bal);
    __syncthreads();
    if (tid == 0) {
        int cnt = 0;
        #pragma unroll
        for (int i = 0; i < 8; i++) cnt += sc[i];
        g_lenp[b][c] = cnt;
        __threadfence();
        unsigned old = atomicAdd(&g_cnt_len, 1u);
        isLast = (old == 4 * BB - 1);
    }
    __syncthreads();
    if (!isLast) return;

    __shared__ int sl[BB];
    for (int bb = tid; bb < BB; bb += 256) {
        volatile int* lp = (volatile int*)g_lenp[bb];
        int len = lp[0] + lp[1] + lp[2] + lp[3];
        sl[bb] = len;
        g_len[bb] = len;
    }
    __syncthreads();
    for (int bb = tid; bb < BB; bb += 256) {
        int len = sl[bb];
        int r = 0;
        #pragma unroll 8
        for (int cc = 0; cc < BB; cc++) {
            int lc = sl[cc];
            r += (lc > len) || (lc == len && cc < bb);
        }
        g_task[r] = bb;
    }
}

// ---------------- gold partials: one thread per (b, s) -------------------
__global__ void k_gold2(const void* mask,
                        const float* __restrict__ feats,
                        const int* __restrict__ tags,
                        const float* __restrict__ tr) {
    int b   = blockIdx.x >> 2;
    int c   = blockIdx.x & 3;
    int tid = threadIdx.x;       // 256
    int s   = (c << 8) + tid;
    __shared__ double sg[8];

    bool on, onNext;
    if (g_isU8) {
        const unsigned char* p = (const unsigned char*)mask + (size_t)b * SS;
        on = p[s] != 0;
        onNext = (s + 1 < SS) ? (p[s + 1] != 0) : false;
    } else {
        const unsigned int* p = (const unsigned int*)mask + (size_t)b * SS;
        on = p[s] != 0;
        onNext = (s + 1 < SS) ? (p[s + 1] != 0) : false;
    }

    double term = 0.0;
    if (on) {
        const int* tg = tags + (size_t)b * SS;
        int tag  = tg[s];
        int prev = (s == 0) ? START_TAG : tg[s - 1];
        term = (double)feats[((size_t)b * SS + s) * TT + tag]
             + (double)tr[prev * TT + tag];
        if (!onNext)
            term += (double)tr[tag * TT + END_TAG];
    }
    #pragma unroll
    for (int o = 16; o; o >>= 1) term += __shfl_xor_sync(0xffffffffu, term, o);
    if ((tid & 31) == 0) sg[tid >> 5] = term;
    __syncthreads();
    if (tid == 0) {
        double acc = 0.0;
        #pragma unroll
        for (int i = 0; i < 8; i++) acc += sg[i];
        g_goldp[b][c] = acc;
    }
}

// ---------------- fused fwd+bwd scan: ONE warp per sequence --------------
// The two directions are independent equal-length chains; interleaving them
// in one warp fills each chain's stall windows with the other's instructions
// (the kernel is latency-bound at issue=22%, so per-superstep wall ~= max of
// the two, not the sum). 512 CTAs -> <1 warp/SMSP -> no issue contention.
__global__ void __launch_bounds__(32, 1) k_main(const float* __restrict__ feats,
                                                const float* __restrict__ tr) {
    const int b = g_task[blockIdx.x];     // LPT order
    const int t = threadIdx.x;            // 0..31
    const bool act = (t < 25);
    const int tcl = act ? t : 24;
    const int jA = act ? 2 * t : 48;
    const int jB = act ? 2 * t + 1 : 49;
    __shared__ __align__(16) u32 shqF[2][32];
    __shared__ __align__(16) u32 shqB[2][32];

    const int len = g_len[b];
    const int m = (len - 1) >> 1;         // fwd steps: s=1..m
    const int N = len - 1 - m;            // bwd iters: k=0..N-1 (N = m or m+1)
    const int L = m + 1;
    const float* fb = feats + (size_t)b * SS * TT;
    const ull L2E2 = f2pack(LOG2E, LOG2E);
    float uFA, uFB, uBA, uBB;
    int KtotF = 0, KtotB = 0;

    // E tables: fwd columns + bwd rows, bf16x2 packed
    u32 EpFA[25], EpFB[25], EpBA[25], EpBB[25];
    #pragma unroll
    for (int c = 0; c < 25; c++) {
        EpFA[c] = g_EcBF[jA][c];
        EpFB[c] = g_EcBF[jB][c];
        EpBA[c] = g_ErBF[jA][c];
        EpBB[c] = g_ErBF[jB][c];
    }

    // ---- fwd init: part0 = feats[b,0,:] + trans[START,:] ----
    float p0A = act ? (fb[jA] + tr[START_TAG * TT + jA]) : -1e30f;
    float p0B = act ? (fb[jB] + tr[START_TAG * TT + jB]) : -1e30f;
    float mx = fmaxf(p0A, p0B);
    #pragma unroll
    for (int o = 16; o; o >>= 1)
        mx = fmaxf(mx, __shfl_xor_sync(0xffffffffu, mx, o));
    const float m0 = mx;
    uFA = act ? ex2((p0A - m0) * LOG2E) : 0.0f;
    uFB = act ? ex2((p0B - m0) * LOG2E) : 0.0f;
    shqF[0][t] = packbf(uFA, uFB);

    // ---- bwd init: beta_{len-1} = ef_{len-1} * E[:,END] ----
    float EendA = g_E[jA * TT + END_TAG];
    float EendB = g_E[jB * TT + END_TAG];
    if (len >= 2) {
        const float* fl = fb + (size_t)(len - 1) * TT;
        uBA = ex2(fl[jA] * LOG2E) * EendA;
        uBB = ex2(fl[jB] * LOG2E) * EendB;
    } else {
        uBA = EendA; uBB = EendB;
    }
    if (!act) { uBA = 0.f; uBB = 0.f; }
    shqB[0][t] = packbf(uBA, uBB);
    __syncwarp();

    // ---- prefetch streams (distance 4 each), pre-scaled by log2e ----
    const float2* pe = (const float2*)fb + tcl;   // stride 26 float2/step
    ull fF0 = 0, fF1 = 0, fF2 = 0, fF3 = 0;
    if (1 < L) { float2 v = pe[1 * 26]; fF0 = f2mul(f2pack(v.x, v.y), L2E2); }
    if (2 < L) { float2 v = pe[2 * 26]; fF1 = f2mul(f2pack(v.x, v.y), L2E2); }
    if (3 < L) { float2 v = pe[3 * 26]; fF2 = f2mul(f2pack(v.x, v.y), L2E2); }
    if (4 < L) { float2 v = pe[4 * 26]; fF3 = f2mul(f2pack(v.x, v.y), L2E2); }
    ull fB0 = 0, fB1 = 0, fB2 = 0, fB3 = 0;
    if (N >= 2) { float2 v = pe[(size_t)(len - 2) * 26]; fB0 = f2mul(f2pack(v.x, v.y), L2E2); }
    if (N >= 3) { float2 v = pe[(size_t)(len - 3) * 26]; fB1 = f2mul(f2pack(v.x, v.y), L2E2); }
    if (N >= 4) { float2 v = pe[(size_t)(len - 4) * 26]; fB2 = f2mul(f2pack(v.x, v.y), L2E2); }
    if (N >= 5) { float2 v = pe[(size_t)(len - 5) * 26]; fB3 = f2mul(f2pack(v.x, v.y), L2E2); }

    int s = 1, k = 0;

#define LOADQ(ARR, SRC, QW) {                                                 \
        const uint4* q4_ = (const uint4*)ARR[SRC];                            \
        uint4 w0_ = q4_[0], w1_ = q4_[1], w2_ = q4_[2], w3_ = q4_[3],         \
              w4_ = q4_[4], w5_ = q4_[5];                                     \
        QW[0] = w0_.x;  QW[1] = w0_.y;  QW[2] = w0_.z;  QW[3] = w0_.w;        \
        QW[4] = w1_.x;  QW[5] = w1_.y;  QW[6] = w1_.z;  QW[7] = w1_.w;        \
        QW[8] = w2_.x;  QW[9] = w2_.y;  QW[10] = w2_.z; QW[11] = w2_.w;       \
        QW[12] = w3_.x; QW[13] = w3_.y; QW[14] = w3_.z; QW[15] = w3_.w;       \
        QW[16] = w4_.x; QW[17] = w4_.y; QW[18] = w4_.z; QW[19] = w4_.w;       \
        QW[20] = w5_.x; QW[21] = w5_.y; QW[22] = w5_.z; QW[23] = w5_.w;       \
        QW[24] = ARR[SRC][24]; }

// fused superstep: one fwd step + one bwd step, single syncwarp
#define FBSTEP(SRC, DST, RN) {                                                \
        float2 fcF = f2unpack(fF0);                                           \
        float efFA = ex2(fcF.x), efFB = ex2(fcF.y);                           \
        fF0 = fF1; fF1 = fF2; fF2 = fF3;                                      \
        { int sp = s + 4; float2 nv = make_float2(0.f, 0.f);                  \
          if (sp < L) nv = pe[sp * 26];                                       \
          fF3 = f2mul(f2pack(nv.x, nv.y), L2E2); }                            \
        float2 fcB = f2unpack(fB0);                                           \
        float efBA = ex2(fcB.x), efBB = ex2(fcB.y);                           \
        fB0 = fB1; fB1 = fB2; fB2 = fB3;                                      \
        { int kk = k + 4; float2 nv = make_float2(0.f, 0.f);                  \
          if (kk <= N - 2) nv = pe[(size_t)(len - 2 - kk) * 26];              \
          fB3 = f2mul(f2pack(nv.x, nv.y), L2E2); }                            \
        u32 qwF[25]; LOADQ(shqF, SRC, qwF)                                    \
        u32 qwB[25]; LOADQ(shqB, SRC, qwB)                                    \
        float preFA, preFB, preBA, preBB;                                     \
        if (RN) {                                                             \
            int exF = ((int)((qwF[0] >> 7) & 0xFFu)) - 127; KtotF += exF;     \
            float scF = __int_as_float((127 - exF) << 23);                    \
            int exB = ((int)((qwB[0] >> 7) & 0xFFu)) - 127; KtotB += exB;     \
            float scB = __int_as_float((127 - exB) << 23);                    \
            preFA = scF * efFA; preFB = scF * efFB;                           \
            preBA = scB * efBA; preBB = scB * efBB;                           \
        } else { preFA = efFA; preFB = efFB; preBA = efBA; preBB = efBB; }    \
        uFA = matvecbf(qwF, EpFA) * preFA;                                    \
        uFB = matvecbf(qwF, EpFB) * preFB;                                    \
        uBA = matvecbf(qwB, EpBA) * preBA;                                    \
        uBB = matvecbf(qwB, EpBB) * preBB;                                    \
        shqF[DST][t] = packbf(uFA, uFB);                                      \
        shqB[DST][t] = packbf(uBA, uBB);                                      \
        __syncwarp();                                                         \
        s++; k++;                                                             \
    }

// lone bwd step (N == m+1 remainder)
#define BONLY(SRC, DST) {                                                     \
        float2 fcB = f2unpack(fB0);                                           \
        float efBA = ex2(fcB.x), efBB = ex2(fcB.y);                           \
        u32 qwB[25]; LOADQ(shqB, SRC, qwB)                                    \
        int exB = ((int)((qwB[0] >> 7) & 0xFFu)) - 127; KtotB += exB;         \
        float scB = __int_as_float((127 - exB) << 23);                        \
        float preBA = scB * efBA, preBB = scB * efBB;                         \
        uBA = matvecbf(qwB, EpBA) * preBA;                                    \
        uBB = matvecbf(qwB, EpBB) * preBB;                                    \
        shqB[DST][t] = packbf(uBA, uBB);                                      \
        __syncwarp();                                                         \
    }

    int j = 0;
    while (j + 2 <= m) { FBSTEP(0, 1, 1) FBSTEP(1, 0, 0) j += 2; }
    if (j < m) { FBSTEP(0, 1, 1) }
    if (N > m) {
        if (m & 1) { BONLY(1, 0) } else { BONLY(0, 1) }
    }
#undef FBSTEP
#undef BONLY
#undef LOADQ

    if (act) {
        ((float2*)g_alpha[b])[t] = make_float2(uFA, uFB);
        ((float2*)g_beta[b])[t]  = make_float2(uBA, uBB);
    }
    if (t == 0) { g_Ka[b] = KtotF; g_Kb[b] = KtotB; g_m0[b] = m0; }
}

// ---------------- combine + fused final reduction (last block) -----------
__global__ void k_combine(float* out) {
    int b = blockIdx.x;
    int l = threadIdx.x;   // 32
    __shared__ unsigned lastFlag;
    double d = (double)g_alpha[b][l] * (double)g_beta[b][l];
    if (l < 18)
        d += (double)g_alpha[b][l + 32] * (double)g_beta[b][l + 32];
    #pragma unroll
    for (int o = 16; o; o >>= 1) d += __shfl_xor_sync(0xffffffffu, d, o);
    if (l == 0) {
        double gold = g_goldp[b][0] + g_goldp[b][1]
                    + g_goldp[b][2] + g_goldp[b][3];
        double logZ = (double)g_m0[b] +
                      (double)(g_Ka[b] + g_Kb[b]) * LN2 + log(d);
        g_final[b] = logZ - gold;
        __threadfence();
        lastFlag = (atomicAdd(&g_cnt_fin, 1u) == BB - 1);
    }
    __syncwarp();
    unsigned isLast = __shfl_sync(0xffffffffu, lastFlag, 0);
    if (isLast) {
        volatile double* gf = (volatile double*)g_final;
        double a = 0.0;
        #pragma unroll
        for (int k = 0; k < BB / 32; k++) a += gf[l + 32 * k];
        #pragma unroll
        for (int o = 16; o; o >>= 1) a += __shfl_xor_sync(0xffffffffu, a, o);
        if (l == 0) out[0] = (float)a;
    }
}

// ---------------- launch (fork-join: gold2 overlaps k_main) ----------------
extern "C" void kernel_launch(void* const* d_in, const int* in_sizes, int n_in,
                              void* d_out, int out_size) {
    const float* feats = (const float*)d_in[0];
    const void*  mask  = d_in[1];
    const int*   tags  = (const int*)d_in[2];
    const float* tr    = (const float*)d_in[3];
    float* out = (float*)d_out;

    cudaStream_t s2 = 0;
    cudaEvent_t evA = 0, evB = 0;
    bool forked =
        (cudaStreamCreateWithFlags(&s2, cudaStreamNonBlocking) == cudaSuccess) &&
        (cudaEventCreateWithFlags(&evA, cudaEventDisableTiming) == cudaSuccess) &&
        (cudaEventCreateWithFlags(&evB, cudaEventDisableTiming) == cudaSuccess);

    k_detect<<<1, 256>>>(mask, tr);
    k_len<<<4 * BB, 256>>>(mask);         // fused rank in last block

    if (forked) {
        cudaEventRecord(evA, 0);
        cudaStreamWaitEvent(s2, evA, 0);
        k_gold2<<<4 * BB, 256, 0, s2>>>(mask, feats, tags, tr);
        k_main<<<BB, 32>>>(feats, tr);
        cudaEventRecord(evB, s2);
        cudaStreamWaitEvent(0, evB, 0);
    } else {
        k_gold2<<<4 * BB, 256>>>(mask, feats, tags, tr);
        k_main<<<BB, 32>>>(feats, tr);
    }

    k_combine<<<BB, 32>>>(out);           // fused final reduce in last block

    if (forked) {
        cudaEventDestroy(evA);
        cudaEventDestroy(evB);
        cudaStreamDestroy(s2);
    }
}

// round 15
// speedup vs baseline: 1.4835x; 1.4835x over previous
#include <cuda_runtime.h>
#include <math.h>

#define BB 512
#define SS 1024
#define TT 52
#define START_TAG 50
#define END_TAG 51
#define LOG2E 1.4426950408889634f
#define LN2 0.6931471805599453

typedef unsigned long long ull;

// ---------------- device scratch (no allocations allowed) ----------------
__device__ __align__(16) float g_E[TT * TT];    // exp(transitions)
__device__ __align__(16) float g_ET[TT * TT];   // transposed copy
__device__ int    g_isU8;
__device__ __align__(16) int g_lenp[BB][4];     // per-chunk length partials
__device__ int    g_len[BB];                    // final lengths
__device__ int    g_task[BB];                   // seq ids, length-descending
__device__ __align__(8) float g_alpha[BB][64];  // slots 50..63 never written (stay 0)
__device__ __align__(8) float g_beta[BB][64];
__device__ int    g_Ka[BB], g_Kb[BB];
__device__ float  g_m0[BB];
__device__ double g_goldp[BB][4];
__device__ double g_final[BB];                  // per-seq logZ (gold applied later)
__device__ unsigned g_cnt_len;
__device__ unsigned g_pairCnt[BB];              // per-sequence completion tickets

// ---------------- packed f32x2 helpers (Blackwell) ----------------
__device__ __forceinline__ ull f2pack(float lo, float hi) {
    ull r;
    asm("mov.b64 %0, {%1, %2};" : "=l"(r) : "f"(lo), "f"(hi));
    return r;
}
__device__ __forceinline__ float2 f2unpack(ull a) {
    float2 r;
    asm("mov.b64 {%0, %1}, %2;" : "=f"(r.x), "=f"(r.y) : "l"(a));
    return r;
}
__device__ __forceinline__ float f2lo(ull a) {
    float r;
    asm("{ .reg .b32 hi; mov.b64 {%0, hi}, %1; }" : "=f"(r) : "l"(a));
    return r;
}
__device__ __forceinline__ ull f2fma(ull a, ull b, ull c) {
    ull d;
    asm("fma.rn.f32x2 %0, %1, %2, %3;" : "=l"(d) : "l"(a), "l"(b), "l"(c));
    return d;
}
__device__ __forceinline__ ull f2mul(ull a, ull b) {
    ull d;
    asm("mul.rn.f32x2 %0, %1, %2;" : "=l"(d) : "l"(a), "l"(b));
    return d;
}
__device__ __forceinline__ ull f2add(ull a, ull b) {
    ull d;
    asm("add.rn.f32x2 %0, %1, %2;" : "=l"(d) : "l"(a), "l"(b));
    return d;
}
__device__ __forceinline__ float ex2(float x) {
    float y;
    asm("ex2.approx.ftz.f32 %0, %1;" : "=f"(y) : "f"(x));
    return y;
}

// matvec over i=0..49 (25 packed pairs), 4 accumulators
__device__ __forceinline__ float matvec25(const ulonglong2* qv, const ull* Ep) {
    ull a0 = f2mul(qv[0].x, Ep[0]);
    ull a1 = f2mul(qv[0].y, Ep[1]);
    ull a2 = f2mul(qv[1].x, Ep[2]);
    ull a3 = f2mul(qv[1].y, Ep[3]);
    #pragma unroll
    for (int c = 2; c < 12; c++) {
        if (c & 1) {
            a2 = f2fma(qv[c].x, Ep[2 * c],     a2);
            a3 = f2fma(qv[c].y, Ep[2 * c + 1], a3);
        } else {
            a0 = f2fma(qv[c].x, Ep[2 * c],     a0);
            a1 = f2fma(qv[c].y, Ep[2 * c + 1], a1);
        }
    }
    a0 = f2fma(qv[12].x, Ep[24], a0);   // pair (48,49)
    a2 = f2add(a2, a3);
    a0 = f2add(a0, a1);
    a0 = f2add(a0, a2);
    float2 h = f2unpack(a0);
    return h.x + h.y;
}

// ---------------- mask dtype + E / E^T + counter reset ----------------
__global__ void k_detect(const void* mask, const float* __restrict__ tr) {
    int tid = threadIdx.x;     // 256
    if (tid == 0) g_cnt_len = 0;
    for (int i = tid; i < BB; i += 256) g_pairCnt[i] = 0;
    if (tid < 32) {
        const unsigned char* p = (const unsigned char*)mask;
        int any = 0;
        for (int b = tid; b < BB; b += 32)
            any |= (int)p[(size_t)b * SS + 1];
        #pragma unroll
        for (int o = 16; o; o >>= 1) any |= __shfl_xor_sync(0xffffffffu, any, o);
        if (tid == 0) g_isU8 = (any != 0);
    }
    for (int idx = tid; idx < TT * TT; idx += 256) {
        float e = expf(tr[idx]);
        g_E[idx] = e;
        g_ET[(idx % TT) * TT + (idx / TT)] = e;
    }
}

// ---------------- length partials + fused rank (last block) --------------
__global__ void k_len(const void* mask) {
    int b   = blockIdx.x >> 2;
    int c   = blockIdx.x & 3;
    int tid = threadIdx.x;       // 256
    int s   = (c << 8) + tid;
    __shared__ int sc[8];
    __shared__ bool isLast;
    bool on;
    if (g_isU8) on = ((const unsigned char*)mask)[(size_t)b * SS + s] != 0;
    else        on = ((const unsigned int*)mask)[(size_t)b * SS + s] != 0;
    unsigned bal = __ballot_sync(0xffffffffu, on);
    if ((tid & 31) == 0) sc[tid >> 5] = __popc(bal);
    __syncthreads();
    if (tid == 0) {
        int cnt = 0;
        #pragma unroll
        for (int i = 0; i < 8; i++) cnt += sc[i];
        g_lenp[b][c] = cnt;
        __threadfence();
        unsigned old = atomicAdd(&g_cnt_len, 1u);
        isLast = (old == 4 * BB - 1);
    }
    __syncthreads();
    if (!isLast) return;

    // ---- rank (LPT order): runs once, after all partials visible ----
    __shared__ int sl[BB];
    for (int bb = tid; bb < BB; bb += 256) {
        volatile int* lp = (volatile int*)g_lenp[bb];
        int len = lp[0] + lp[1] + lp[2] + lp[3];
        sl[bb] = len;
        g_len[bb] = len;
    }
    __syncthreads();
    for (int bb = tid; bb < BB; bb += 256) {
        int len = sl[bb];
        int r = 0;
        #pragma unroll 8
        for (int cc = 0; cc < BB; cc++) {
            int lc = sl[cc];
            r += (lc > len) || (lc == len && cc < bb);
        }
        g_task[r] = bb;
    }
}

// ---------------- gold partials: one thread per (b, s) -------------------
__global__ void k_gold2(const void* mask,
                        const float* __restrict__ feats,
                        const int* __restrict__ tags,
                        const float* __restrict__ tr) {
    int b   = blockIdx.x >> 2;
    int c   = blockIdx.x & 3;
    int tid = threadIdx.x;       // 256
    int s   = (c << 8) + tid;
    __shared__ double sg[8];

    bool on, onNext;
    if (g_isU8) {
        const unsigned char* p = (const unsigned char*)mask + (size_t)b * SS;
        on = p[s] != 0;
        onNext = (s + 1 < SS) ? (p[s + 1] != 0) : false;
    } else {
        const unsigned int* p = (const unsigned int*)mask + (size_t)b * SS;
        on = p[s] != 0;
        onNext = (s + 1 < SS) ? (p[s + 1] != 0) : false;
    }

    double term = 0.0;
    if (on) {
        const int* tg = tags + (size_t)b * SS;
        int tag  = tg[s];
        int prev = (s == 0) ? START_TAG : tg[s - 1];
        term = (double)feats[((size_t)b * SS + s) * TT + tag]
             + (double)tr[prev * TT + tag];
        if (!onNext)                         // last valid position
            term += (double)tr[tag * TT + END_TAG];
    }
    #pragma unroll
    for (int o = 16; o; o >>= 1) term += __shfl_xor_sync(0xffffffffu, term, o);
    if ((tid & 31) == 0) sg[tid >> 5] = term;
    __syncthreads();
    if (tid == 0) {
        double acc = 0.0;
        #pragma unroll
        for (int i = 0; i < 8; i++) acc += sg[i];
        g_goldp[b][c] = acc;
    }
}

// ---------------- forward/backward scan, single-warp CTAs ----------------
// Task (cta>>1) = rank in length-descending order (LPT striping); dir=cta&1.
// f32x2 matvec (bf16 and fused-direction variants both measured slower).
// Step barrier is __syncthreads(): in a 1-warp CTA BAR.SYNC has a 3-cycle
// floor AND drains pending STS, vs ~23 cyc for WARPSYNC (__syncwarp).
// The second-finishing CTA of each pair computes logZ_b inline (per-pair
// atomic ticket) — no separate combine kernel.
__global__ void __launch_bounds__(32, 1) k_main(const float* __restrict__ feats,
                                                const float* __restrict__ tr) {
    const int cta = blockIdx.x;
    const int b = g_task[cta >> 1];
    const bool isFwd = (cta & 1) == 0;
    const int t = threadIdx.x;            // 0..31
    const bool act = (t < 25);
    const int tcl = act ? t : 24;
    const int jA = act ? 2 * t : 48;
    const int jB = act ? 2 * t + 1 : 49;
    __shared__ __align__(16) float shq[2][64];

    const int len = g_len[b];             // broadcast, 1 LDG
    const int m = (len - 1) >> 1;
    const float* fb = feats + (size_t)b * SS * TT;
    const ull L2E2 = f2pack(LOG2E, LOG2E);
    float uA, uB;
    int Ktot = 0;

    if (isFwd) {
        const int L = m + 1;              // steps s=1..m
        ull EpA[25], EpB[25];
        const ull* EcA = (const ull*)(g_ET + jA * TT);
        const ull* EcB = (const ull*)(g_ET + jB * TT);
        #pragma unroll
        for (int c = 0; c < 25; c++) { EpA[c] = EcA[c]; EpB[c] = EcB[c]; }

        float p0A = act ? (fb[jA] + tr[START_TAG * TT + jA]) : -1e30f;
        float p0B = act ? (fb[jB] + tr[START_TAG * TT + jB]) : -1e30f;
        float mx = fmaxf(p0A, p0B);
        #pragma unroll
        for (int o = 16; o; o >>= 1)
            mx = fmaxf(mx, __shfl_xor_sync(0xffffffffu, mx, o));
        const float m0 = mx;
        uA = act ? ex2((p0A - m0) * LOG2E) : 0.0f;
        uB = act ? ex2((p0B - m0) * LOG2E) : 0.0f;
        ((float2*)shq[0])[t] = make_float2(uA, uB);
        __syncthreads();

        const float2* pe = (const float2*)fb + tcl;   // stride 26 float2/step
        ull fl0 = 0, fl1 = 0, fl2 = 0, fl3 = 0;
        if (1 < L) { float2 v = pe[1 * 26]; fl0 = f2mul(f2pack(v.x, v.y), L2E2); }
        if (2 < L) { float2 v = pe[2 * 26]; fl1 = f2mul(f2pack(v.x, v.y), L2E2); }
        if (3 < L) { float2 v = pe[3 * 26]; fl2 = f2mul(f2pack(v.x, v.y), L2E2); }
        if (4 < L) { float2 v = pe[4 * 26]; fl3 = f2mul(f2pack(v.x, v.y), L2E2); }

#define FSTEP(SRC, DST, RN) {                                                 \
        float2 fc = f2unpack(fl0);                                            \
        float efA = ex2(fc.x), efB = ex2(fc.y);                               \
        fl0 = fl1; fl1 = fl2; fl2 = fl3;                                      \
        int sp = s + 4;                                                       \
        float2 nv = make_float2(0.f, 0.f);                                    \
        if (sp < L) nv = pe[sp * 26];                                         \
        fl3 = f2mul(f2pack(nv.x, nv.y), L2E2);                                \
        const ulonglong2* q8 = (const ulonglong2*)shq[SRC];                   \
        ulonglong2 qv[13];                                                    \
        _Pragma("unroll") for (int c = 0; c < 13; c++) qv[c] = q8[c];         \
        float preA, preB;                                                     \
        if (RN) {                                                             \
            float q0 = f2lo(qv[0].x);                                         \
            int exq = ((__float_as_int(q0) >> 23) & 0xFF) - 127;              \
            Ktot += exq;                                                      \
            float scale = __int_as_float((127 - exq) << 23);                  \
            preA = scale * efA; preB = scale * efB;                           \
        } else { preA = efA; preB = efB; }                                    \
        uA = matvec25(qv, EpA) * preA;                                        \
        uB = matvec25(qv, EpB) * preB;                                        \
        ((float2*)shq[DST])[t] = make_float2(uA, uB);                         \
        __syncthreads();                                                      \
        s++;                                                                  \
    }
        int s = 1;
        while (s + 1 < L) { FSTEP(0, 1, 1) FSTEP(1, 0, 0) }
        if (s < L) { FSTEP(0, 1, 1) }
#undef FSTEP
        if (act) ((float2*)g_alpha[b])[t] = make_float2(uA, uB);
        if (t == 0) { g_Ka[b] = Ktot; g_m0[b] = m0; }
    } else {
        const int N = len - 1 - m;        // iterations: s = len-2 .. m
        ull EpA[25], EpB[25];
        const ull* ErA = (const ull*)(g_E + jA * TT);
        const ull* ErB = (const ull*)(g_E + jB * TT);
        #pragma unroll
        for (int c = 0; c < 25; c++) { EpA[c] = ErA[c]; EpB[c] = ErB[c]; }

        float EendA = g_E[jA * TT + END_TAG];
        float EendB = g_E[jB * TT + END_TAG];
        if (len >= 2) {
            const float* fl = fb + (size_t)(len - 1) * TT;
            uA = ex2(fl[jA] * LOG2E) * EendA;
            uB = ex2(fl[jB] * LOG2E) * EendB;
        } else {
            uA = EendA; uB = EendB;       // len==1: beta = E[:,END], no ef
        }
        if (!act) { uA = 0.f; uB = 0.f; }
        ((float2*)shq[0])[t] = make_float2(uA, uB);
        __syncthreads();

        const float2* pb = (const float2*)fb + tcl;
        ull fl0 = 0, fl1 = 0, fl2 = 0, fl3 = 0;
        if (N >= 2) { float2 v = pb[(size_t)(len - 2) * 26]; fl0 = f2mul(f2pack(v.x, v.y), L2E2); }
        if (N >= 3) { float2 v = pb[(size_t)(len - 3) * 26]; fl1 = f2mul(f2pack(v.x, v.y), L2E2); }
        if (N >= 4) { float2 v = pb[(size_t)(len - 4) * 26]; fl2 = f2mul(f2pack(v.x, v.y), L2E2); }
        if (N >= 5) { float2 v = pb[(size_t)(len - 5) * 26]; fl3 = f2mul(f2pack(v.x, v.y), L2E2); }

#define BSTEP(SRC, DST, RN) {                                                 \
        float2 fc = f2unpack(fl0);                                            \
        float efA = ex2(fc.x), efB = ex2(fc.y);                               \
        fl0 = fl1; fl1 = fl2; fl2 = fl3;                                      \
        int kk = k + 4;                                                       \
        float2 nv = make_float2(0.f, 0.f);                                    \
        if (kk <= N - 2) nv = pb[(size_t)(len - 2 - kk) * 26];                \
        fl3 = f2mul(f2pack(nv.x, nv.y), L2E2);                                \
        const ulonglong2* q8 = (const ulonglong2*)shq[SRC];                   \
        ulonglong2 qv[13];                                                    \
        _Pragma("unroll") for (int c = 0; c < 13; c++) qv[c] = q8[c];         \
        float preA, preB;                                                     \
        if (RN) {                                                             \
            float q0 = f2lo(qv[0].x);                                         \
            int exq = ((__float_as_int(q0) >> 23) & 0xFF) - 127;              \
            Ktot += exq;                                                      \
            float scale = __int_as_float((127 - exq) << 23);                  \
            preA = scale * efA; preB = scale * efB;                           \
        } else { preA = efA; preB = efB; }                                    \
        uA = matvec25(qv, EpA) * preA;                                        \
        uB = matvec25(qv, EpB) * preB;                                        \
        ((float2*)shq[DST])[t] = make_float2(uA, uB);                         \
        __syncthreads();                                                      \
        k++;                                                                  \
    }
        int k = 0;
        while (k + 1 < N) { BSTEP(0, 1, 1) BSTEP(1, 0, 0) }
        if (k < N) { BSTEP(0, 1, 1) }
#undef BSTEP
        if (act) ((float2*)g_beta[b])[t] = make_float2(uA, uB);
        if (t == 0) g_Kb[b] = Ktot;
    }

    // ---- per-pair combine: second finisher computes logZ_b inline ----
    __syncthreads();
    __threadfence();
    unsigned old = 0;
    if (t == 0) old = atomicAdd(&g_pairCnt[b], 1u);
    old = __shfl_sync(0xffffffffu, old, 0);
    if (old == 1u) {
        volatile float* va = (volatile float*)g_alpha[b];
        volatile float* vb = (volatile float*)g_beta[b];
        double d = (double)va[t] * (double)vb[t];
        if (t < 18)
            d += (double)va[t + 32] * (double)vb[t + 32];
        #pragma unroll
        for (int o = 16; o; o >>= 1) d += __shfl_xor_sync(0xffffffffu, d, o);
        if (t == 0) {
            int Ka = *(volatile int*)&g_Ka[b];
            int Kb = *(volatile int*)&g_Kb[b];
            float m0v = *(volatile float*)&g_m0[b];
            g_final[b] = (double)m0v + (double)(Ka + Kb) * LN2 + log(d);
        }
    }
}

// ---------------- finisher: sum(logZ_b - gold_b) ----------------
__global__ void k_fin(float* out) {
    __shared__ double sh[16];
    int tid = threadIdx.x;  // 512 threads
    double g = g_goldp[tid][0] + g_goldp[tid][1]
             + g_goldp[tid][2] + g_goldp[tid][3];
    double a = g_final[tid] - g;
    #pragma unroll
    for (int o = 16; o; o >>= 1) a += __shfl_xor_sync(0xffffffffu, a, o);
    if ((tid & 31) == 0) sh[tid >> 5] = a;
    __syncthreads();
    if (tid < 32) {
        double v = (tid < 16) ? sh[tid] : 0.0;
        #pragma unroll
        for (int o = 8; o; o >>= 1) v += __shfl_xor_sync(0xffffffffu, v, o);
        if (tid == 0) out[0] = (float)v;
    }
}

// ---------------- launch (fork-join: gold2 overlaps k_main) ----------------
extern "C" void kernel_launch(void* const* d_in, const int* in_sizes, int n_in,
                              void* d_out, int out_size) {
    const float* feats = (const float*)d_in[0];
    const void*  mask  = d_in[1];
    const int*   tags  = (const int*)d_in[2];
    const float* tr    = (const float*)d_in[3];
    float* out = (float*)d_out;

    cudaStream_t s2 = 0;
    cudaEvent_t evA = 0, evB = 0;
    bool forked =
        (cudaStreamCreateWithFlags(&s2, cudaStreamNonBlocking) == cudaSuccess) &&
        (cudaEventCreateWithFlags(&evA, cudaEventDisableTiming) == cudaSuccess) &&
        (cudaEventCreateWithFlags(&evB, cudaEventDisableTiming) == cudaSuccess);

    k_detect<<<1, 256>>>(mask, tr);
    k_len<<<4 * BB, 256>>>(mask);         // fused rank in last block

    if (forked) {
        cudaEventRecord(evA, 0);
        cudaStreamWaitEvent(s2, evA, 0);
        k_gold2<<<4 * BB, 256, 0, s2>>>(mask, feats, tags, tr);
        k_main<<<2 * BB, 32>>>(feats, tr);
        cudaEventRecord(evB, s2);
        cudaStreamWaitEvent(0, evB, 0);
    } else {
        k_gold2<<<4 * BB, 256>>>(mask, feats, tags, tr);
        k_main<<<2 * BB, 32>>>(feats, tr);
    }

    k_fin<<<1, 512>>>(out);               // after join: gold partials ready

    if (forked) {
        cudaEventDestroy(evA);
        cudaEventDestroy(evB);
        cudaStreamDestroy(s2);
    }
}